// round 7
// baseline (speedup 1.0000x reference)
#include <cuda_runtime.h>
#include <cuda_bf16.h>
#include <math.h>

#define SEQ_LEN 16384
#define ENC_H   2048
#define DEC_H   2048

#define KA_THREADS 512
#define NBLK       512                       // kA blocks
#define ROWS_PER_BLK (SEQ_LEN / NBLK)        // 32
#define CHUNK      8                         // rows per chunk
#define NCHUNKS    (ROWS_PER_BLK / CHUNK)    // 4

// Scratch (device globals — no allocation allowed)
__device__ float g_v[ENC_H];
__device__ float g_ctx[NBLK * ENC_H];        // 4 MB
__device__ float g_m[NBLK];
__device__ float g_z[NBLK];

// ---------------------------------------------------------------------------
// Kernel 1: v[e] = sum_d W[e,d] * dec[d]   (block per row: 2048 x 128)
// ---------------------------------------------------------------------------
__global__ __launch_bounds__(128) void k1_gemv(const float* __restrict__ W,
                                               const float* __restrict__ dec) {
    int s    = blockIdx.x;
    int t    = threadIdx.x;
    int warp = t >> 5;
    int lane = t & 31;
    const float4* row = reinterpret_cast<const float4*>(W + (size_t)s * DEC_H);
    const float4* d4  = reinterpret_cast<const float4*>(dec);

    float4 a[4], b[4];
    #pragma unroll
    for (int i = 0; i < 4; ++i) {
        a[i] = __ldcs(&row[t + 128 * i]);
        b[i] = __ldg(&d4[t + 128 * i]);
    }
    float acc = 0.0f;
    #pragma unroll
    for (int i = 0; i < 4; ++i)
        acc += a[i].x * b[i].x + a[i].y * b[i].y + a[i].z * b[i].z + a[i].w * b[i].w;
    #pragma unroll
    for (int o = 16; o > 0; o >>= 1) acc += __shfl_xor_sync(0xffffffffu, acc, o);
    __shared__ float red[4];
    if (lane == 0) red[warp] = acc;
    __syncthreads();
    if (t == 0) g_v[s] = red[0] + red[1] + red[2] + red[3];
}

// ---------------------------------------------------------------------------
// Kernel A: fused scores + online softmax + weighted accumulate.
//   512 threads/block (thread = one float4 column), 32 rows per block in
//   4 chunks of 8. High occupancy (~60 regs) for latency hiding.
// ---------------------------------------------------------------------------
__global__ __launch_bounds__(KA_THREADS, 2) void kA_fused(const float* __restrict__ enc) {
    __shared__ float s_red[16][CHUNK];   // per-warp partial dots
    __shared__ float s_sc[CHUNK];        // final scores for the chunk
    int t    = threadIdx.x;
    int warp = t >> 5;                   // 16 warps
    int lane = t & 31;
    size_t s0 = (size_t)blockIdx.x * ROWS_PER_BLK;

    const float4* v4 = reinterpret_cast<const float4*>(g_v);
    float4 v = __ldg(&v4[t]);

    float4 acc = make_float4(0.f, 0.f, 0.f, 0.f);
    float m = -INFINITY, z = 0.0f;

    for (int c = 0; c < NCHUNKS; ++c) {
        // bulk load this chunk: 8 independent LDG.128 per thread (streaming)
        float4 x[CHUNK];
        #pragma unroll
        for (int r = 0; r < CHUNK; ++r) {
            const float4* row = reinterpret_cast<const float4*>(
                enc + (s0 + c * CHUNK + r) * ENC_H);
            x[r] = __ldcs(&row[t]);
        }

        // per-thread 4-wide dots, warp reduce
        #pragma unroll
        for (int r = 0; r < CHUNK; ++r) {
            float d = x[r].x * v.x + x[r].y * v.y + x[r].z * v.z + x[r].w * v.w;
            #pragma unroll
            for (int o = 16; o > 0; o >>= 1) d += __shfl_xor_sync(0xffffffffu, d, o);
            if (lane == 0) s_red[warp][r] = d;
        }
        __syncthreads();

        // warp 0 lanes 0..7: sum 16 warp-partials per row -> s_sc
        if (warp == 0 && lane < CHUNK) {
            float sum = 0.0f;
            #pragma unroll
            for (int w = 0; w < 16; ++w) sum += s_red[w][lane];
            s_sc[lane] = sum;
        }
        __syncthreads();

        // all threads: identical online softmax update + accumulate
        float sc[CHUNK];
        #pragma unroll
        for (int r = 0; r < CHUNK; ++r) sc[r] = s_sc[r];
        float nm = m;
        #pragma unroll
        for (int r = 0; r < CHUNK; ++r) nm = fmaxf(nm, sc[r]);
        float f = __expf(m - nm);        // first chunk: exp(-inf)=0
        acc.x *= f; acc.y *= f; acc.z *= f; acc.w *= f;
        z *= f;
        #pragma unroll
        for (int r = 0; r < CHUNK; ++r) {
            float w = __expf(sc[r] - nm);
            z += w;
            acc.x += w * x[r].x; acc.y += w * x[r].y;
            acc.z += w * x[r].z; acc.w += w * x[r].w;
        }
        m = nm;
        __syncthreads();                 // protect s_red/s_sc before next chunk
    }

    reinterpret_cast<float4*>(g_ctx + (size_t)blockIdx.x * ENC_H)[t] = acc;
    if (t == 0) { g_m[blockIdx.x] = m; g_z[blockIdx.x] = z; }
}

// ---------------------------------------------------------------------------
// Kernel B: single-kernel combine (proven R3 shape).
//   128 blocks x 128 thr; warp per float4-column, lanes stride the 512
//   partial blocks (16 loads/lane).
// ---------------------------------------------------------------------------
__global__ __launch_bounds__(128) void kB_combine(float* __restrict__ out) {
    __shared__ float s_e[NBLK];
    __shared__ float s_red[4];
    __shared__ float s_M, s_invZ;
    int t    = threadIdx.x;
    int warp = t >> 5;
    int lane = t & 31;

    float m = fmaxf(g_m[t], fmaxf(g_m[t + 128], fmaxf(g_m[t + 256], g_m[t + 384])));
    #pragma unroll
    for (int o = 16; o > 0; o >>= 1) m = fmaxf(m, __shfl_xor_sync(0xffffffffu, m, o));
    if (lane == 0) s_red[warp] = m;
    __syncthreads();
    if (t == 0)
        s_M = fmaxf(fmaxf(s_red[0], s_red[1]), fmaxf(s_red[2], s_red[3]));
    __syncthreads();
    float M = s_M;

    float zsum = 0.0f;
    #pragma unroll
    for (int i = t; i < NBLK; i += 128) {
        float e = __expf(g_m[i] - M);
        s_e[i] = e;
        zsum += e * g_z[i];
    }
    #pragma unroll
    for (int o = 16; o > 0; o >>= 1) zsum += __shfl_xor_sync(0xffffffffu, zsum, o);
    __syncthreads();
    if (lane == 0) s_red[warp] = zsum;
    __syncthreads();
    if (t == 0)
        s_invZ = 1.0f / (s_red[0] + s_red[1] + s_red[2] + s_red[3]);
    __syncthreads();

    int col4 = blockIdx.x * 4 + warp;
    const float4* ctx = reinterpret_cast<const float4*>(g_ctx);
    float4 acc = make_float4(0.f, 0.f, 0.f, 0.f);
    #pragma unroll
    for (int b = lane; b < NBLK; b += 32) {
        float w  = s_e[b];
        float4 c = ctx[(size_t)b * (ENC_H / 4) + col4];
        acc.x += w * c.x; acc.y += w * c.y; acc.z += w * c.z; acc.w += w * c.w;
    }
    #pragma unroll
    for (int o = 16; o > 0; o >>= 1) {
        acc.x += __shfl_xor_sync(0xffffffffu, acc.x, o);
        acc.y += __shfl_xor_sync(0xffffffffu, acc.y, o);
        acc.z += __shfl_xor_sync(0xffffffffu, acc.z, o);
        acc.w += __shfl_xor_sync(0xffffffffu, acc.w, o);
    }
    if (lane == 0) {
        float inv = s_invZ;
        float4 r = make_float4(acc.x * inv, acc.y * inv, acc.z * inv, acc.w * inv);
        reinterpret_cast<float4*>(out)[col4] = r;
    }
}

extern "C" void kernel_launch(void* const* d_in, const int* in_sizes, int n_in,
                              void* d_out, int out_size) {
    const float* enc = (const float*)d_in[0];   // [16384, 2048]
    const float* dec = (const float*)d_in[1];   // [1, 2048]
    const float* W   = (const float*)d_in[2];   // [2048, 2048]
    float* out = (float*)d_out;                 // [1, 2048]

    k1_gemv<<<ENC_H, 128>>>(W, dec);
    kA_fused<<<NBLK, KA_THREADS>>>(enc);
    kB_combine<<<128, 128>>>(out);
}